// round 9
// baseline (speedup 1.0000x reference)
#include <cuda_runtime.h>

// Fixed shapes from reference setup_inputs
#define BB    32        // batch
#define TT    4000      // frames per batch
#define NB    65        // nbands
#define LF    129       // FIR length = 2*NB-1
#define FS    80        // framesize (hop)
#define FPB   50        // frames per block tile (kernel B)
#define EF    54        // staged frames (t0-2 .. t0+51)
#define TILES 80        // TT / FPB
#define OUTW  320000    // TT*FS
#define WROW  164       // firwin row stride: 15 zeros + 129 taps + 20 zeros (164 % 32 = 4)
#define WPAD  15        // left zero pad
#define NTHR  256
#define NFRM  (BB*TT)   // 128000 flat frames
#define ZPST  68        // smem H/T row stride in kernel A
#define ANF   64        // frames per chunk in kernel A
#define NCH   4         // chunks per block in kernel A
#define ZGRID 500       // 500 blocks x 4 chunks x 64 frames = 128000
#define XSZ   4860      // swizzled x staging: 4320 + (4320/32)*4

// Pre-expanded firwin rows; pads NEVER written -> stay zero (BSS zero-init).
__device__ __align__(16) float g_w[(size_t)NFRM * WROW];   // 84 MB

__device__ __forceinline__ unsigned long long pk2(float a, float b) {
    unsigned long long r;
    asm("mov.b64 %0, {%1, %2};" : "=l"(r) : "f"(a), "f"(b));
    return r;
}
__device__ __forceinline__ void upk2(unsigned long long v, float& a, float& b) {
    asm("mov.b64 {%0, %1}, %2;" : "=f"(a), "=f"(b) : "l"(v));
}
__device__ __forceinline__ unsigned long long ffma2(unsigned long long a,
                                                    unsigned long long b,
                                                    unsigned long long c) {
    unsigned long long d;
    asm("fma.rn.f32x2 %0, %1, %2, %3;" : "=l"(d) : "l"(a), "l"(b), "l"(c));
    return d;
}

// ---------------- Kernel A: expanded firwin rows ----------------
// zp[d] = sum_k H[k]*T[d][k];  w[j] = zp[|j-64|]*hann[j].
// Warp w: frames f0=8w..8w+7; lane l: d = l, l+33 -> taps {64-l, 64+l, 31-l, 97+l}.
__global__ void __launch_bounds__(NTHR)
zp_kernel(const float* __restrict__ H) {
    __shared__ __align__(16) float sTa[NB * ZPST];   // 17680 B
    __shared__ __align__(16) float sHa[ANF * ZPST];  // 17408 B
    __shared__ float sHann[LF + 3];

    const int tid = threadIdx.x;

    for (int i = tid; i < NB * NB; i += NTHR) {
        int d = i / NB, k = i - (i / NB) * NB;
        int m = (k * d) % LF;
        float c = cospif(2.0f * (float)m * (1.0f / 129.0f));
        sTa[d * ZPST + k] = (k == 0) ? (1.0f / 129.0f) : (2.0f / 129.0f) * c;
        if (i < LF)
            sHann[i] = 0.5f - 0.5f * cospif(2.0f * (float)i * (1.0f / 129.0f));
    }

    float hreg[17];
    {
        size_t base = (size_t)(blockIdx.x * ANF) * NB;
        #pragma unroll
        for (int q = 0; q < 17; ++q) {
            int i = tid + NTHR * q;
            hreg[q] = (i < ANF * NB) ? H[base + i] : 0.0f;
        }
    }
    __syncthreads();

    const int w = tid >> 5, l = tid & 31;
    const int f0 = w * 8;
    const float* tr0 = &sTa[l * ZPST];
    const float* tr1 = &sTa[(l + 33) * ZPST];
    const float h0a = sHann[64 - l];
    const float h0b = sHann[64 + l];
    const float h1a = sHann[31 - l];
    const float h1b = sHann[97 + l];
    const float h32a = sHann[32], h32b = sHann[96];

    for (int ch = 0; ch < NCH; ++ch) {
        const int n0 = blockIdx.x * ANF + ch * (ZGRID * ANF);

        __syncthreads();
        #pragma unroll
        for (int q = 0; q < 17; ++q) {
            int i = tid + NTHR * q;
            if (i < ANF * NB) sHa[(i / NB) * ZPST + (i % NB)] = hreg[q];
        }
        __syncthreads();

        if (ch + 1 < NCH) {
            size_t base = (size_t)(blockIdx.x * ANF + (ch + 1) * (ZGRID * ANF)) * NB;
            #pragma unroll
            for (int q = 0; q < 17; ++q) {
                int i = tid + NTHR * q;
                hreg[q] = (i < ANF * NB) ? H[base + i] : 0.0f;
            }
        }

        float acc0[8] = {0,0,0,0,0,0,0,0};
        float acc1[8] = {0,0,0,0,0,0,0,0};

        #pragma unroll 4
        for (int kc = 0; kc < 16; ++kc) {
            int k0 = kc * 4;
            float4 t0 = *reinterpret_cast<const float4*>(tr0 + k0);
            float4 t1 = *reinterpret_cast<const float4*>(tr1 + k0);
            #pragma unroll
            for (int j = 0; j < 8; ++j) {
                float4 hv = *reinterpret_cast<const float4*>(&sHa[(f0 + j) * ZPST + k0]);
                float a0 = acc0[j], a1 = acc1[j];
                a0 = fmaf(hv.x, t0.x, a0); a1 = fmaf(hv.x, t1.x, a1);
                a0 = fmaf(hv.y, t0.y, a0); a1 = fmaf(hv.y, t1.y, a1);
                a0 = fmaf(hv.z, t0.z, a0); a1 = fmaf(hv.z, t1.z, a1);
                a0 = fmaf(hv.w, t0.w, a0); a1 = fmaf(hv.w, t1.w, a1);
                acc0[j] = a0; acc1[j] = a1;
            }
        }
        {
            float t0s = tr0[64], t1s = tr1[64];
            #pragma unroll
            for (int j = 0; j < 8; ++j) {
                float hs = sHa[(f0 + j) * ZPST + 64];
                acc0[j] = fmaf(hs, t0s, acc0[j]);
                acc1[j] = fmaf(hs, t1s, acc1[j]);
            }
        }

        #pragma unroll
        for (int j = 0; j < 8; ++j) {
            size_t row = (size_t)(n0 + f0 + j) * WROW + WPAD;
            g_w[row + 64 - l] = acc0[j] * h0a;
            g_w[row + 64 + l] = acc0[j] * h0b;
            g_w[row + 31 - l] = acc1[j] * h1a;
            g_w[row + 97 + l] = acc1[j] * h1b;
        }
        if (tid < ANF) {
            const float* tr = &sTa[32 * ZPST];
            const float* hr = &sHa[tid * ZPST];
            float s = 0.0f;
            #pragma unroll 5
            for (int k = 0; k < NB; ++k) s = fmaf(hr[k], tr[k], s);
            size_t row = (size_t)(n0 + tid) * WROW + WPAD;
            g_w[row + 32] = s * h32a;
            g_w[row + 96] = s * h32b;
        }
    }
}

// ---------------- Kernel B: conv + overlap-add (f32x2 packed) ----------------
__global__ void __launch_bounds__(NTHR, 3)
fng_main(const float* __restrict__ noise, float* __restrict__ out) {
    __shared__ __align__(16) float sW[EF * WROW];  // 35424 B
    __shared__ __align__(16) float sX[XSZ];        // 19440 B

    const int tid  = threadIdx.x;
    const int b    = blockIdx.x / TILES;
    const int tile = blockIdx.x - b * TILES;
    const int t0   = tile * FPB;

    // ---- stage firwin rows: pure linear float4 copy ----
    {
        float4* dst = reinterpret_cast<float4*>(sW);
        const int n4 = EF * WROW / 4;                  // 2214
        if (tile == 0) {
            const float4* s0 = reinterpret_cast<const float4*>(&g_w[(size_t)b * TT * WROW]);
            const int pad4 = 2 * WROW / 4;             // 82
            for (int i = tid; i < n4; i += NTHR)
                dst[i] = (i < pad4) ? make_float4(0.f,0.f,0.f,0.f) : s0[i - pad4];
        } else if (tile == TILES - 1) {
            const float4* src = reinterpret_cast<const float4*>(
                &g_w[(size_t)(b * TT + t0 - 2) * WROW]);
            const int lim4 = 52 * WROW / 4;            // 2132
            for (int i = tid; i < n4; i += NTHR)
                dst[i] = (i < lim4) ? src[i] : make_float4(0.f,0.f,0.f,0.f);
        } else {
            const float4* src = reinterpret_cast<const float4*>(
                &g_w[(size_t)(b * TT + t0 - 2) * WROW]);
            for (int i = tid; i < n4; i += NTHR)
                dst[i] = src[i];
        }
    }
    // ---- stage x = 2*noise-1: linear float4 load, swizzled float4 store ----
    {
        const int n4 = EF * FS / 4;                    // 1080
        const float4* src = reinterpret_cast<const float4*>(
            &noise[(size_t)(b * TT + (tile == 0 ? 0 : t0 - 2)) * FS]);
        const int pad4 = (tile == 0) ? (2 * FS / 4) : 0;           // 40 lead zeros on tile 0
        const int lim4 = (tile == TILES - 1) ? (52 * FS / 4) : n4; // 1040 valid on last tile
        for (int i = tid; i < n4; i += NTHR) {
            float4 v = (i >= pad4 && i < lim4) ? src[i - pad4] : make_float4(0.5f,0.5f,0.5f,0.5f);
            int i0 = i * 4;
            float4 x = make_float4(2.f*v.x-1.f, 2.f*v.y-1.f, 2.f*v.z-1.f, 2.f*v.w-1.f);
            *reinterpret_cast<float4*>(&sX[i0 + ((i0 >> 5) << 2)]) = x;
        }
    }
    __syncthreads();

    // ---- conv + OLA: thread owns 16 consecutive pre-trim outputs q = 80*t0 + 16g + r ----
    // 18 chunks of 8 samples. Pair outputs (2i, 2i+1): one fma.rn.f32x2 per pair per sample.
    const int groups = (tile == TILES - 1) ? 254 : 250;
    for (int g = tid; g < groups; g += NTHR) {
        if (tile == 0 && g < 4) continue;      // trimmed head (q < 64)
        const int ql0 = g * 16;
        const int sl0 = ql0 + 32;
        int f = sl0 / FS;
        int rem = sl0 - f * FS;
        int cb = (rem == 0) ? 10 : ((FS - rem) >> 3);
        const float* wr = &sW[f * WROW];
        unsigned long long acc[8];
        #pragma unroll
        for (int i = 0; i < 8; ++i) acc[i] = 0ull;

        #pragma unroll 1
        for (int c = 0; c < 18; ++c) {
            if (c == cb) { wr += WROW; cb += 10; }
            int slc = sl0 + 8 * c;
            int xi = slc + ((slc >> 5) << 2);
            float4 xa = *reinterpret_cast<const float4*>(&sX[xi]);
            float4 xb = *reinterpret_cast<const float4*>(&sX[xi + 4]);
            const float* bp = wr + (136 - 8 * c);   // band[m] = tap j = (121-8c)+m
            float4 w0 = *reinterpret_cast<const float4*>(bp);
            float4 w1 = *reinterpret_cast<const float4*>(bp + 4);
            float4 w2 = *reinterpret_cast<const float4*>(bp + 8);
            float4 w3 = *reinterpret_cast<const float4*>(bp + 12);
            float4 w4 = *reinterpret_cast<const float4*>(bp + 16);
            float4 w5 = *reinterpret_cast<const float4*>(bp + 20);
            float bf[24] = {w0.x,w0.y,w0.z,w0.w, w1.x,w1.y,w1.z,w1.w,
                            w2.x,w2.y,w2.z,w2.w, w3.x,w3.y,w3.z,w3.w,
                            w4.x,w4.y,w4.z,w4.w, w5.x,w5.y,w5.z,w5.w};
            // P[k] = (bf[2k], bf[2k+1]) for odd u;  Q[k] = (bf[2k+1], bf[2k+2]) for even u
            unsigned long long P[11], Q[11];
            #pragma unroll
            for (int k = 0; k < 11; ++k) {
                P[k] = pk2(bf[2*k],   bf[2*k+1]);
                Q[k] = pk2(bf[2*k+1], bf[2*k+2]);
            }
            float xs[8] = {xa.x, xa.y, xa.z, xa.w, xb.x, xb.y, xb.z, xb.w};
            #pragma unroll
            for (int u = 0; u < 8; ++u) {
                unsigned long long xp = pk2(xs[u], xs[u]);
                if (u & 1) {
                    const int o = (7 - u) >> 1;
                    #pragma unroll
                    for (int i = 0; i < 8; ++i) acc[i] = ffma2(xp, P[i + o], acc[i]);
                } else {
                    const int o = (6 - u) >> 1;
                    #pragma unroll
                    for (int i = 0; i < 8; ++i) acc[i] = ffma2(xp, Q[i + o], acc[i]);
                }
            }
        }

        float o[16];
        #pragma unroll
        for (int i = 0; i < 8; ++i) upk2(acc[i], o[2*i], o[2*i+1]);
        int p = t0 * FS + ql0 - 64;            // trimmed position, multiple of 16
        float* op = &out[(size_t)b * OUTW + p];
        *reinterpret_cast<float4*>(op)      = make_float4(o[0],  o[1],  o[2],  o[3]);
        *reinterpret_cast<float4*>(op + 4)  = make_float4(o[4],  o[5],  o[6],  o[7]);
        *reinterpret_cast<float4*>(op + 8)  = make_float4(o[8],  o[9],  o[10], o[11]);
        *reinterpret_cast<float4*>(op + 12) = make_float4(o[12], o[13], o[14], o[15]);
    }
}

extern "C" void kernel_launch(void* const* d_in, const int* in_sizes, int n_in,
                              void* d_out, int out_size) {
    (void)in_sizes; (void)n_in; (void)out_size;
    const float* H     = (const float*)d_in[0];
    const float* noise = (const float*)d_in[1];
    float* out         = (float*)d_out;

    zp_kernel<<<ZGRID, NTHR>>>(H);
    fng_main<<<BB * TILES, NTHR>>>(noise, out);
}

// round 10
// speedup vs baseline: 1.0376x; 1.0376x over previous
#include <cuda_runtime.h>

// Fixed shapes from reference setup_inputs
#define BB    32        // batch
#define TT    4000      // frames per batch
#define NB    65        // nbands
#define LF    129       // FIR length = 2*NB-1
#define FS    80        // framesize (hop)
#define FPB   25        // frames per block tile (kernel B)
#define EF    28        // staged frames (t0-2 .. t0+25)
#define TILES 160       // TT / FPB
#define OUTW  320000    // TT*FS
#define WROW  148       // padded firwin row stride: 11 zeros + 129 taps + 8 zeros
#define WPAD  11        // left zero pad (band base 132-8c float4-aligned)
#define NTHR  256
#define NFRM  (BB*TT)   // 128000 flat frames
#define ZPST  68        // padded T/H row stride (float4-aligned)
#define ANF   64        // frames per block in kernel A
#define ZGRID 2000      // NFRM / ANF
#define XSZ   2520      // swizzled x staging size

// Cosine table, padded rows [65][68]; built once by init_T.
__device__ __align__(16) float g_T[NB * ZPST];
// Pre-expanded firwin rows; pads NEVER written -> stay zero (BSS zero-init).
__device__ __align__(16) float g_w[(size_t)NFRM * WROW];   // 75.8 MB

// ---------------- init: cosine table ----------------
__global__ void init_T() {
    int i = blockIdx.x * blockDim.x + threadIdx.x;
    if (i < NB * ZPST) {
        int d = i / ZPST, k = i - d * ZPST;
        float v = 0.0f;
        if (k < NB) {
            int m = (k * d) % LF;
            float c = cospif(2.0f * (float)m * (1.0f / 129.0f));
            v = (k == 0) ? (1.0f / 129.0f) : (2.0f / 129.0f) * c;
        }
        g_T[i] = v;
    }
}

__device__ __forceinline__ float hannf(int j) {
    return 0.5f - 0.5f * cospif(2.0f * (float)j * (1.0f / 129.0f));
}

// ---------------- Kernel A: expanded firwin rows ----------------
// zp[d] = sum_k H[k]*T[d][k];  w[j] = zp[|j-64|]*hann[j].
// One 64-frame chunk per block (2000 blocks -> ~4% tail imbalance).
// Warp w: frames f0=8w..8w+7; lane l: d = l, l+33 -> taps {64-l, 64+l, 31-l, 97+l}.
__global__ void __launch_bounds__(NTHR)
zp_kernel(const float* __restrict__ H) {
    __shared__ __align__(16) float sTa[NB * ZPST];   // 17680 B
    __shared__ __align__(16) float sHa[ANF * ZPST];  // 17408 B

    const int tid = threadIdx.x;
    const int n0  = blockIdx.x * ANF;

    // stage T from L2 (pure float4 copy)
    {
        const float4* src = reinterpret_cast<const float4*>(g_T);
        float4* dst = reinterpret_cast<float4*>(sTa);
        for (int i = tid; i < NB * ZPST / 4; i += NTHR) dst[i] = src[i];
    }
    // stage H rows (scalar scatter into padded rows)
    for (int i = tid; i < ANF * NB; i += NTHR) {
        int f = i / NB, k = i - f * NB;
        sHa[f * ZPST + k] = H[(size_t)n0 * NB + i];
    }
    __syncthreads();

    const int w = tid >> 5, l = tid & 31;
    const int f0 = w * 8;
    const float* tr0 = &sTa[l * ZPST];
    const float* tr1 = &sTa[(l + 33) * ZPST];
    const float h0a = hannf(64 - l);
    const float h0b = hannf(64 + l);
    const float h1a = hannf(31 - l);
    const float h1b = hannf(97 + l);

    float acc0[8] = {0,0,0,0,0,0,0,0};
    float acc1[8] = {0,0,0,0,0,0,0,0};

    #pragma unroll 4
    for (int kc = 0; kc < 16; ++kc) {
        int k0 = kc * 4;
        float4 t0 = *reinterpret_cast<const float4*>(tr0 + k0);
        float4 t1 = *reinterpret_cast<const float4*>(tr1 + k0);
        #pragma unroll
        for (int j = 0; j < 8; ++j) {
            float4 hv = *reinterpret_cast<const float4*>(&sHa[(f0 + j) * ZPST + k0]);
            float a0 = acc0[j], a1 = acc1[j];
            a0 = fmaf(hv.x, t0.x, a0); a1 = fmaf(hv.x, t1.x, a1);
            a0 = fmaf(hv.y, t0.y, a0); a1 = fmaf(hv.y, t1.y, a1);
            a0 = fmaf(hv.z, t0.z, a0); a1 = fmaf(hv.z, t1.z, a1);
            a0 = fmaf(hv.w, t0.w, a0); a1 = fmaf(hv.w, t1.w, a1);
            acc0[j] = a0; acc1[j] = a1;
        }
    }
    {   // k = 64 tail
        float t0s = tr0[64], t1s = tr1[64];
        #pragma unroll
        for (int j = 0; j < 8; ++j) {
            float hs = sHa[(f0 + j) * ZPST + 64];
            acc0[j] = fmaf(hs, t0s, acc0[j]);
            acc1[j] = fmaf(hs, t1s, acc1[j]);
        }
    }

    // expanded firwin stores (4 coalesced groups per frame row)
    #pragma unroll
    for (int j = 0; j < 8; ++j) {
        size_t row = (size_t)(n0 + f0 + j) * WROW + WPAD;
        g_w[row + 64 - l] = acc0[j] * h0a;
        g_w[row + 64 + l] = acc0[j] * h0b;
        g_w[row + 31 - l] = acc1[j] * h1a;
        g_w[row + 97 + l] = acc1[j] * h1b;
    }
    // d = 32 epilogue: threads 0..63, one frame each -> taps j = 32, 96
    if (tid < ANF) {
        const float* tr = &sTa[32 * ZPST];
        const float* hr = &sHa[tid * ZPST];
        float s = 0.0f;
        #pragma unroll 5
        for (int k = 0; k < NB; ++k) s = fmaf(hr[k], tr[k], s);
        size_t row = (size_t)(n0 + tid) * WROW + WPAD;
        g_w[row + 32] = s * hannf(32);
        g_w[row + 96] = s * hannf(96);
    }
}

// ---------------- Kernel B: conv + overlap-add (R8, at scalar-FMA roofline) ----------------
__global__ void __launch_bounds__(NTHR)
fng_main(const float* __restrict__ noise, float* __restrict__ out) {
    __shared__ __align__(16) float sW[EF * WROW];  // 16576 B (pre-expanded rows)
    __shared__ __align__(16) float sX[XSZ];        // 10080 B (linear + (s>>5)*4 swizzle)

    const int tid  = threadIdx.x;
    const int b    = blockIdx.x / TILES;
    const int tile = blockIdx.x - b * TILES;
    const int t0   = tile * FPB;

    // ---- stage firwin rows: pure linear float4 copy ----
    {
        float4* dst = reinterpret_cast<float4*>(sW);
        const int n4 = EF * WROW / 4;                  // 1036
        if (tile == 0) {
            const float4* s0 = reinterpret_cast<const float4*>(&g_w[(size_t)b * TT * WROW]);
            const int pad4 = 2 * WROW / 4;             // 74
            for (int i = tid; i < n4; i += NTHR)
                dst[i] = (i < pad4) ? make_float4(0.f,0.f,0.f,0.f) : s0[i - pad4];
        } else if (tile == TILES - 1) {
            const float4* src = reinterpret_cast<const float4*>(
                &g_w[(size_t)(b * TT + t0 - 2) * WROW]);
            const int lim4 = 27 * WROW / 4;            // 999
            for (int i = tid; i < n4; i += NTHR)
                dst[i] = (i < lim4) ? src[i] : make_float4(0.f,0.f,0.f,0.f);
        } else {
            const float4* src = reinterpret_cast<const float4*>(
                &g_w[(size_t)(b * TT + t0 - 2) * WROW]);
            for (int i = tid; i < n4; i += NTHR)
                dst[i] = src[i];
        }
    }
    // ---- stage x = 2*noise-1: linear float4 load, swizzled float4 store ----
    {
        const int n4 = EF * FS / 4;                    // 560
        const float4* src = reinterpret_cast<const float4*>(
            &noise[(size_t)(b * TT + (tile == 0 ? 0 : t0 - 2)) * FS]);
        const int pad4 = (tile == 0) ? (2 * FS / 4) : 0;
        const int lim4 = (tile == TILES - 1) ? (27 * FS / 4) : n4;
        for (int i = tid; i < n4; i += NTHR) {
            float4 v = (i >= pad4 && i < lim4) ? src[i - pad4] : make_float4(0.5f,0.5f,0.5f,0.5f);
            int i0 = i * 4;
            float4 x = make_float4(2.f*v.x-1.f, 2.f*v.y-1.f, 2.f*v.z-1.f, 2.f*v.w-1.f);
            *reinterpret_cast<float4*>(&sX[i0 + ((i0 >> 5) << 2)]) = x;
        }
    }
    __syncthreads();

    // ---- conv + OLA: thread owns 8 consecutive pre-trim outputs q = 80*t0 + 8g + r ----
    const int groups = (tile == TILES - 1) ? 258 : 250;
    for (int g = tid; g < groups; g += NTHR) {
        if (tile == 0 && g < 8) continue;      // trimmed head
        const int ql0 = g * 8;
        const int sl0 = ql0 + 32;
        int f = sl0 / FS;
        int rem = sl0 - f * FS;
        int cb = (rem == 0) ? 10 : ((FS - rem) >> 3);
        const float* wr = &sW[f * WROW];
        float acc[8] = {0,0,0,0,0,0,0,0};

        #pragma unroll 1
        for (int c = 0; c < 17; ++c) {
            if (c == cb) { wr += WROW; cb += 10; }
            int slc = sl0 + 8 * c;
            int xi = slc + ((slc >> 5) << 2);
            float4 xa = *reinterpret_cast<const float4*>(&sX[xi]);
            float4 xb = *reinterpret_cast<const float4*>(&sX[xi + 4]);
            const float* bp = wr + (132 - 8 * c);
            float4 b0 = *reinterpret_cast<const float4*>(bp);
            float4 b1 = *reinterpret_cast<const float4*>(bp + 4);
            float4 b2 = *reinterpret_cast<const float4*>(bp + 8);
            float4 b3 = *reinterpret_cast<const float4*>(bp + 12);
            float band[16] = {b0.x,b0.y,b0.z,b0.w, b1.x,b1.y,b1.z,b1.w,
                              b2.x,b2.y,b2.z,b2.w, b3.x,b3.y,b3.z,b3.w};
            float xs[8] = {xa.x, xa.y, xa.z, xa.w, xb.x, xb.y, xb.z, xb.w};
            #pragma unroll
            for (int u = 0; u < 8; ++u) {
                float xv = xs[u];
                #pragma unroll
                for (int r = 0; r < 8; ++r)
                    acc[r] = fmaf(xv, band[7 + r - u], acc[r]);
            }
        }

        int p = t0 * FS + ql0 - 64;            // trimmed position, multiple of 8
        float* op = &out[(size_t)b * OUTW + p];
        *reinterpret_cast<float4*>(op)     = make_float4(acc[0], acc[1], acc[2], acc[3]);
        *reinterpret_cast<float4*>(op + 4) = make_float4(acc[4], acc[5], acc[6], acc[7]);
    }
}

extern "C" void kernel_launch(void* const* d_in, const int* in_sizes, int n_in,
                              void* d_out, int out_size) {
    (void)in_sizes; (void)n_in; (void)out_size;
    const float* H     = (const float*)d_in[0];
    const float* noise = (const float*)d_in[1];
    float* out         = (float*)d_out;

    init_T<<<(NB * ZPST + 255) / 256, 256>>>();
    zp_kernel<<<ZGRID, NTHR>>>(H);
    fng_main<<<BB * TILES, NTHR>>>(noise, out);
}